// round 1
// baseline (speedup 1.0000x reference)
#include <cuda_runtime.h>
#include <cstdint>

#define BDIM 128      // batch
#define NDIM 1024     // N (square)
#define BM   64       // b rows per block
#define BN   16       // j cols per block
#define BK   64       // k (i) chunk
#define NTHREADS 256
#define NCHUNK (NDIM / BK)     // 16
#define XS_STRIDE (BK + 4)     // 68: 16B-aligned rows, conflict-free scalar/vec4 reads

__device__ __forceinline__ void cp_async16(uint32_t dst_smem, const void* src) {
    asm volatile("cp.async.cg.shared.global [%0], [%1], 16;\n"
                 :: "r"(dst_smem), "l"(src));
}
__device__ __forceinline__ void cp_commit() {
    asm volatile("cp.async.commit_group;\n" ::: "memory");
}
__device__ __forceinline__ void cp_wait1() {
    asm volatile("cp.async.wait_group 1;\n" ::: "memory");
}

__global__ void __launch_bounds__(NTHREADS, 1)
tropical_dense_kernel(const float* __restrict__ x,
                      const float* __restrict__ w,
                      const float* __restrict__ bias,
                      float* __restrict__ out)
{
    __shared__ float xs[2][BM][XS_STRIDE];   // x chunk: [b_local][k_local]
    __shared__ float ws[2][BK][BN];          // W chunk: [k_local][j_local]

    const int tid = threadIdx.x;
    const int j0  = blockIdx.x * BN;   // 0..1023 step 16  (64 tiles)
    const int b0  = blockIdx.y * BM;   // 0 or 64          (2 tiles)

    // compute mapping: thread -> (1 b-row, 4 j-cols)
    const int b_local = tid >> 2;          // 0..63
    const int j4      = (tid & 3) << 2;    // 0,4,8,12

    // load mapping for ws: 1 float4 per thread
    const int wk  = tid >> 2;              // 0..63 (k row)
    const int wc4 = (tid & 3) << 2;        // 0,4,8,12 (j col)

    // ---- prefetch helper (inlined via lambda-like macro pattern) ----
    auto prefetch = [&](int chunk, int buf) {
        const int kbase = chunk * BK;
        // xs: 64 rows x 64 floats = 1024 float4; 4 per thread
        #pragma unroll
        for (int r = 0; r < 4; r++) {
            int idx = tid + NTHREADS * r;
            int bb  = idx >> 4;             // 0..63
            int f4  = (idx & 15) << 2;      // 0..60 step 4
            uint32_t d = (uint32_t)__cvta_generic_to_shared(&xs[buf][bb][f4]);
            cp_async16(d, &x[(b0 + bb) * NDIM + kbase + f4]);
        }
        // ws: 64 rows x 16 floats = 256 float4; 1 per thread
        uint32_t d = (uint32_t)__cvta_generic_to_shared(&ws[buf][wk][wc4]);
        cp_async16(d, &w[(kbase + wk) * NDIM + j0 + wc4]);
    };

    float4 acc;
    acc.x = -__int_as_float(0x7f800000);
    acc.y = acc.x; acc.z = acc.x; acc.w = acc.x;

    prefetch(0, 0);
    cp_commit();

    #pragma unroll 1
    for (int c = 0; c < NCHUNK; c++) {
        const int cur = c & 1;
        if (c + 1 < NCHUNK) prefetch(c + 1, cur ^ 1);
        cp_commit();
        cp_wait1();            // chunk c complete (newest group stays pending)
        __syncthreads();

        const float* xrow = &xs[cur][b_local][0];
        #pragma unroll
        for (int kk = 0; kk < BK; kk += 4) {
            float4 xv = *reinterpret_cast<const float4*>(&xrow[kk]);
            const float* wp = &ws[cur][kk][j4];
            float4 w0 = *reinterpret_cast<const float4*>(wp);
            float4 w1 = *reinterpret_cast<const float4*>(wp + BN);
            float4 w2 = *reinterpret_cast<const float4*>(wp + 2 * BN);
            float4 w3 = *reinterpret_cast<const float4*>(wp + 3 * BN);

            acc.x = fmaxf(acc.x, xv.x - w0.x);
            acc.y = fmaxf(acc.y, xv.x - w0.y);
            acc.z = fmaxf(acc.z, xv.x - w0.z);
            acc.w = fmaxf(acc.w, xv.x - w0.w);

            acc.x = fmaxf(acc.x, xv.y - w1.x);
            acc.y = fmaxf(acc.y, xv.y - w1.y);
            acc.z = fmaxf(acc.z, xv.y - w1.z);
            acc.w = fmaxf(acc.w, xv.y - w1.w);

            acc.x = fmaxf(acc.x, xv.z - w2.x);
            acc.y = fmaxf(acc.y, xv.z - w2.y);
            acc.z = fmaxf(acc.z, xv.z - w2.z);
            acc.w = fmaxf(acc.w, xv.z - w2.w);

            acc.x = fmaxf(acc.x, xv.w - w3.x);
            acc.y = fmaxf(acc.y, xv.w - w3.y);
            acc.z = fmaxf(acc.z, xv.w - w3.z);
            acc.w = fmaxf(acc.w, xv.w - w3.w);
        }
        __syncthreads();
    }

    // epilogue: add bias, vectorized store
    float4 bv = *reinterpret_cast<const float4*>(&bias[j0 + j4]);
    float4 o;
    o.x = acc.x + bv.x;
    o.y = acc.y + bv.y;
    o.z = acc.z + bv.z;
    o.w = acc.w + bv.w;
    *reinterpret_cast<float4*>(&out[(b0 + b_local) * NDIM + j0 + j4]) = o;
}

extern "C" void kernel_launch(void* const* d_in, const int* in_sizes, int n_in,
                              void* d_out, int out_size) {
    const float* x    = (const float*)d_in[0];   // [128, 1024]
    const float* wgt  = (const float*)d_in[1];   // [1024, 1024]
    const float* bias = (const float*)d_in[2];   // [1024]
    float* out = (float*)d_out;                  // [128, 1024]

    dim3 grid(NDIM / BN, BDIM / BM);  // (64, 2) = 128 blocks
    tropical_dense_kernel<<<grid, NTHREADS>>>(x, wgt, bias, out);
}

// round 2
// speedup vs baseline: 1.3910x; 1.3910x over previous
#include <cuda_runtime.h>
#include <cstdint>
#include <math_constants.h>

#define NN   1024     // N (square)
#define BB   128      // batch
#define SPLITK 8
#define KS   (NN / SPLITK)   // 128 k per block
#define BK   16              // k chunk in smem
#define NCH  (KS / BK)       // 8 chunks
#define BM   64              // b tile per block
#define BN   64              // j tile per block
#define XS_STRIDE 68         // 68*4B = 272B rows, 16B aligned, conflict-free

// scratch for split-K partials: [SPLITK][BB][NN] = 4 MB
__device__ float g_partials[SPLITK * BB * NN];

__device__ __forceinline__ void cp_async16(uint32_t dst_smem, const void* src) {
    asm volatile("cp.async.cg.shared.global [%0], [%1], 16;\n"
                 :: "r"(dst_smem), "l"(src));
}
__device__ __forceinline__ void cp_commit() {
    asm volatile("cp.async.commit_group;\n" ::: "memory");
}
__device__ __forceinline__ void cp_wait0() {
    asm volatile("cp.async.wait_group 0;\n" ::: "memory");
}

__global__ void __launch_bounds__(256, 2)
tropical_main(const float* __restrict__ x,
              const float* __restrict__ w)
{
    __shared__ float xs[2][BK][XS_STRIDE];  // x transposed: [k][b]
    __shared__ float ws[2][BK][BN];         // w natural:    [k][j]

    const int tid = threadIdx.x;
    const int tx  = tid & 15;        // j quad index (0..15)
    const int ty  = tid >> 4;        // b quad index (0..15)
    const int j0  = blockIdx.x * BN;
    const int b0  = blockIdx.y * BM;
    const int k0  = blockIdx.z * KS;

    // x load mapping: thread -> (b row, k quad)
    const int lb  = tid & 63;        // 0..63
    const int lkq = (tid >> 6) << 2; // 0,4,8,12
    // w load mapping: thread -> (k row, j quad)
    const int wk  = tid >> 4;        // 0..15
    const int wj  = (tid & 15) << 2; // 0..60

    float acc[4][4];
    #pragma unroll
    for (int r = 0; r < 4; r++)
        #pragma unroll
        for (int c = 0; c < 4; c++)
            acc[r][c] = -CUDART_INF_F;

    // ---- prologue: fill buffer 0 with chunk 0 ----
    {
        float4 xr = *reinterpret_cast<const float4*>(&x[(b0 + lb) * NN + k0 + lkq]);
        xs[0][lkq + 0][lb] = xr.x;
        xs[0][lkq + 1][lb] = xr.y;
        xs[0][lkq + 2][lb] = xr.z;
        xs[0][lkq + 3][lb] = xr.w;
        uint32_t d = (uint32_t)__cvta_generic_to_shared(&ws[0][wk][wj]);
        cp_async16(d, &w[(k0 + wk) * NN + j0 + wj]);
        cp_commit();
        cp_wait0();
        __syncthreads();
    }

    int buf = 0;
    #pragma unroll 1
    for (int c = 0; c < NCH; c++) {
        float4 xn;
        const bool more = (c + 1 < NCH);
        if (more) {
            const int kb = k0 + (c + 1) * BK;
            xn = *reinterpret_cast<const float4*>(&x[(b0 + lb) * NN + kb + lkq]);
            uint32_t d = (uint32_t)__cvta_generic_to_shared(&ws[buf ^ 1][wk][wj]);
            cp_async16(d, &w[(kb + wk) * NN + j0 + wj]);
            cp_commit();
        }

        #pragma unroll
        for (int k = 0; k < BK; k++) {
            float4 xv = *reinterpret_cast<const float4*>(&xs[buf][k][ty << 2]);
            float4 wv = *reinterpret_cast<const float4*>(&ws[buf][k][tx << 2]);
            float xr4[4] = {xv.x, xv.y, xv.z, xv.w};
            float wc4[4] = {wv.x, wv.y, wv.z, wv.w};
            #pragma unroll
            for (int r = 0; r < 4; r++)
                #pragma unroll
                for (int cc = 0; cc < 4; cc++)
                    acc[r][cc] = fmaxf(acc[r][cc], xr4[r] - wc4[cc]);
        }

        if (more) {
            xs[buf ^ 1][lkq + 0][lb] = xn.x;
            xs[buf ^ 1][lkq + 1][lb] = xn.y;
            xs[buf ^ 1][lkq + 2][lb] = xn.z;
            xs[buf ^ 1][lkq + 3][lb] = xn.w;
            cp_wait0();
        }
        __syncthreads();
        buf ^= 1;
    }

    // ---- write partial maxes (no bias yet) ----
    float* p = &g_partials[blockIdx.z * (BB * NN)];
    #pragma unroll
    for (int r = 0; r < 4; r++) {
        float4 o;
        o.x = acc[r][0]; o.y = acc[r][1]; o.z = acc[r][2]; o.w = acc[r][3];
        *reinterpret_cast<float4*>(&p[(b0 + (ty << 2) + r) * NN + j0 + (tx << 2)]) = o;
    }
}

__global__ void __launch_bounds__(256, 4)
tropical_reduce(const float* __restrict__ bias,
                float* __restrict__ out)
{
    const int i = (blockIdx.x * 256 + threadIdx.x) << 2;  // float index, [BB*NN)
    float4 m = *reinterpret_cast<const float4*>(&g_partials[i]);
    #pragma unroll
    for (int s = 1; s < SPLITK; s++) {
        float4 q = *reinterpret_cast<const float4*>(&g_partials[s * (BB * NN) + i]);
        m.x = fmaxf(m.x, q.x);
        m.y = fmaxf(m.y, q.y);
        m.z = fmaxf(m.z, q.z);
        m.w = fmaxf(m.w, q.w);
    }
    const int j = i & (NN - 1);
    float4 bv = *reinterpret_cast<const float4*>(&bias[j]);
    float4 o;
    o.x = m.x + bv.x;
    o.y = m.y + bv.y;
    o.z = m.z + bv.z;
    o.w = m.w + bv.w;
    *reinterpret_cast<float4*>(&out[i]) = o;
}

extern "C" void kernel_launch(void* const* d_in, const int* in_sizes, int n_in,
                              void* d_out, int out_size) {
    const float* x    = (const float*)d_in[0];   // [128, 1024]
    const float* wgt  = (const float*)d_in[1];   // [1024, 1024]
    const float* bias = (const float*)d_in[2];   // [1024]
    float* out = (float*)d_out;                  // [128, 1024]

    dim3 grid(NN / BN, BB / BM, SPLITK);  // (16, 2, 8) = 256 blocks
    tropical_main<<<grid, 256>>>(x, wgt);

    const int total = BB * NN;            // 131072
    tropical_reduce<<<total / 4 / 256, 256>>>(bias, out);
}